// round 2
// baseline (speedup 1.0000x reference)
#include <cuda_runtime.h>
#include <math.h>

#define B_TOK 32768
#define D_DIM 128
#define H_DIM 512
#define E_EXP 16
#define TM 64
#define KH 64
#define NCHUNK (H_DIM / KH)
#define THREADS 256

// ---------------- device scratch (no allocation allowed) ----------------
__device__ int g_cnt[E_EXP];
__device__ int g_tok[E_EXP * B_TOK];

// ---------------- f32x2 helpers (sm_103a packed fp32 pipe) ----------------
__device__ __forceinline__ unsigned long long ffma2(unsigned long long a,
                                                    unsigned long long b,
                                                    unsigned long long c) {
    unsigned long long d;
    asm("fma.rn.f32x2 %0, %1, %2, %3;" : "=l"(d) : "l"(a), "l"(b), "l"(c));
    return d;
}
__device__ __forceinline__ float hsum2(unsigned long long v) {
    unsigned int lo, hi;
    asm("mov.b64 {%0, %1}, %2;" : "=r"(lo), "=r"(hi) : "l"(v));
    return __uint_as_float(lo) + __uint_as_float(hi);
}

// ---------------- kernel 0: reset counters (graph replay safe) ----------------
__global__ void zero_cnt_kernel() {
    if (threadIdx.x < E_EXP) g_cnt[threadIdx.x] = 0;
}

// ---------------- kernel 1: router (argmax of x@wg+bg), warp-aggregated buckets ----
__global__ __launch_bounds__(THREADS) void router_kernel(
    const float* __restrict__ x, const float* __restrict__ wg,
    const float* __restrict__ bg) {
    __shared__ float wgs[D_DIM * E_EXP];
    __shared__ float bgs[E_EXP];
    int tid = threadIdx.x;
    for (int i = tid; i < D_DIM * E_EXP; i += THREADS) wgs[i] = wg[i];
    if (tid < E_EXP) bgs[tid] = bg[tid];
    __syncthreads();

    int b = blockIdx.x * THREADS + tid;
    float acc[E_EXP];
#pragma unroll
    for (int e = 0; e < E_EXP; e++) acc[e] = bgs[e];

    const float4* xr = reinterpret_cast<const float4*>(x) + (size_t)b * (D_DIM / 4);
#pragma unroll 4
    for (int dq = 0; dq < D_DIM / 4; dq++) {
        float4 xv = xr[dq];
#pragma unroll
        for (int e = 0; e < E_EXP; e++) {
            acc[e] += xv.x * wgs[(dq * 4 + 0) * E_EXP + e];
            acc[e] += xv.y * wgs[(dq * 4 + 1) * E_EXP + e];
            acc[e] += xv.z * wgs[(dq * 4 + 2) * E_EXP + e];
            acc[e] += xv.w * wgs[(dq * 4 + 3) * E_EXP + e];
        }
    }
    int best = 0; float bv = acc[0];
#pragma unroll
    for (int e = 1; e < E_EXP; e++)
        if (acc[e] > bv) { bv = acc[e]; best = e; }  // strict > keeps first max (top_k tie rule)

    // warp-aggregated atomic append into per-expert bucket
    unsigned lane = tid & 31;
    unsigned mask = __match_any_sync(0xffffffffu, best);
    int leader = __ffs(mask) - 1;
    int rank = __popc(mask & ((1u << lane) - 1u));
    int base = 0;
    if ((int)lane == leader) base = atomicAdd(&g_cnt[best], __popc(mask));
    base = __shfl_sync(0xffffffffu, base, leader);
    g_tok[best * B_TOK + base + rank] = b;
}

// ---------------- kernel 2: grouped fused MLP ----------------
// CTA = one 64-token tile of one expert. SMEM: Xs[64][128] | Ws (pair-interleaved
// weight chunk, 8192 f) | Hs[64][64] | toks[64]. Both GEMMs run on fma.rn.f32x2.
#define SMEM_FLOATS (TM * D_DIM + 8192 + TM * KH)
#define SMEM_BYTES (SMEM_FLOATS * 4 + TM * 4)

extern __shared__ float smem[];

__global__ __launch_bounds__(THREADS) void moe_kernel(
    const float* __restrict__ x, const float* __restrict__ w1,
    const float* __restrict__ w2, float* __restrict__ out) {
    int e = blockIdx.x;
    int cnt = g_cnt[e];
    int start = blockIdx.y * TM;
    if (start >= cnt) return;
    int ntok = min(TM, cnt - start);
    int tid = threadIdx.x;

    float* Xs = smem;                 // [m][d] row-major, 64*128
    float* Ws = smem + TM * D_DIM;    // pair-interleaved weight chunk, 8192 floats
    float* Hs = Ws + 8192;            // [m][j] row-major, 64*64
    int* toks = (int*)(Hs + TM * KH); // 64 ints

    if (tid < TM) toks[tid] = (tid < ntok) ? g_tok[e * B_TOK + start + tid] : -1;
    __syncthreads();

    // gather X rows (zeros for padded slots)
#pragma unroll
    for (int it = 0; it < 8; it++) {
        int idx = tid + it * THREADS;   // 0..2047
        int m = idx >> 5;               // token in tile
        int q = idx & 31;               // float4 within row
        int t = toks[m];
        float4 v = (t >= 0) ? reinterpret_cast<const float4*>(x)[t * 32 + q]
                            : make_float4(0.f, 0.f, 0.f, 0.f);
        reinterpret_cast<float4*>(Xs)[m * 32 + q] = v;
    }

    const float* w1e = w1 + (size_t)e * D_DIM * H_DIM;
    const float* w2e = w2 + (size_t)e * H_DIM * D_DIM;

    // phase-1 thread map: 16x16 grid, 4m x 4j microtile
    int tx = tid & 15, ty = tid >> 4;
    int j0 = tx * 4, m0 = ty * 4;
    // phase-2 thread map: 32x8 grid, 8m x 4dd microtile
    int dd0 = (tid & 31) * 4, m0b = (tid >> 5) * 8;

    unsigned long long oacc[8][4];
#pragma unroll
    for (int i = 0; i < 8; i++)
#pragma unroll
        for (int j = 0; j < 4; j++) oacc[i][j] = 0ull;

    for (int c = 0; c < NCHUNK; c++) {
        int h0 = c * KH;
        __syncthreads();  // Ws/Hs free of previous-phase readers; Xs stores visible (c==0)

        // ---- load W1 chunk, pair-interleave along d: Ws[(dp*KH + j)*2 + (d&1)]
#pragma unroll
        for (int it = 0; it < 8; it++) {
            int idx = tid + it * THREADS;  // 0..2047
            int d = idx >> 4;              // 0..127
            int q = idx & 15;              // j-quad
            float4 v = reinterpret_cast<const float4*>(w1e + d * H_DIM + h0)[q];
            int dp = d >> 1, ln = d & 1;
            Ws[(dp * KH + q * 4 + 0) * 2 + ln] = v.x;
            Ws[(dp * KH + q * 4 + 1) * 2 + ln] = v.y;
            Ws[(dp * KH + q * 4 + 2) * 2 + ln] = v.z;
            Ws[(dp * KH + q * 4 + 3) * 2 + ln] = v.w;
        }
        __syncthreads();

        // ---- phase 1: Hs = gelu(X @ W1chunk), f32x2 over d-pairs
        unsigned long long acc[4][4];
#pragma unroll
        for (int i = 0; i < 4; i++)
#pragma unroll
            for (int j = 0; j < 4; j++) acc[i][j] = 0ull;

#pragma unroll 8
        for (int dp = 0; dp < D_DIM / 2; dp++) {
            unsigned long long a2[4], b2[4];
#pragma unroll
            for (int mi = 0; mi < 4; mi++)
                a2[mi] = *reinterpret_cast<const unsigned long long*>(
                    &Xs[(m0 + mi) * D_DIM + 2 * dp]);
#pragma unroll
            for (int ji = 0; ji < 4; ji++)
                b2[ji] = *reinterpret_cast<const unsigned long long*>(
                    &Ws[(dp * KH + j0 + ji) * 2]);
#pragma unroll
            for (int mi = 0; mi < 4; mi++)
#pragma unroll
                for (int ji = 0; ji < 4; ji++)
                    acc[mi][ji] = ffma2(a2[mi], b2[ji], acc[mi][ji]);
        }
#pragma unroll
        for (int mi = 0; mi < 4; mi++)
#pragma unroll
            for (int ji = 0; ji < 4; ji++) {
                float h = hsum2(acc[mi][ji]);
                float g = 0.5f * h * (1.0f + erff(h * 0.70710678118654752440f));
                Hs[(m0 + mi) * KH + j0 + ji] = g;
            }
        __syncthreads();

        // ---- load W2 chunk, pair-interleave along j: Ws[(jp*D + dd)*2 + (j&1)]
#pragma unroll
        for (int it = 0; it < 8; it++) {
            int idx = tid + it * THREADS;  // 0..2047
            int j = idx >> 5;              // 0..63
            int q = idx & 31;              // dd-quad
            float4 v = reinterpret_cast<const float4*>(w2e + (size_t)(h0 + j) * D_DIM)[q];
            int jp = j >> 1, ln = j & 1;
            Ws[(jp * D_DIM + q * 4 + 0) * 2 + ln] = v.x;
            Ws[(jp * D_DIM + q * 4 + 1) * 2 + ln] = v.y;
            Ws[(jp * D_DIM + q * 4 + 2) * 2 + ln] = v.z;
            Ws[(jp * D_DIM + q * 4 + 3) * 2 + ln] = v.w;
        }
        __syncthreads();

        // ---- phase 2: out += Hs @ W2chunk, f32x2 over j-pairs (persistent packed acc)
#pragma unroll 8
        for (int jp = 0; jp < KH / 2; jp++) {
            unsigned long long a2[8], b2[4];
#pragma unroll
            for (int mi = 0; mi < 8; mi++)
                a2[mi] = *reinterpret_cast<const unsigned long long*>(
                    &Hs[(m0b + mi) * KH + 2 * jp]);
#pragma unroll
            for (int di = 0; di < 4; di++)
                b2[di] = *reinterpret_cast<const unsigned long long*>(
                    &Ws[(jp * D_DIM + dd0 + di) * 2]);
#pragma unroll
            for (int mi = 0; mi < 8; mi++)
#pragma unroll
                for (int di = 0; di < 4; di++)
                    oacc[mi][di] = ffma2(a2[mi], b2[di], oacc[mi][di]);
        }
    }

    // epilogue: horizontal add of even/odd-j partials, scatter to output rows
#pragma unroll
    for (int mi = 0; mi < 8; mi++) {
        int m = m0b + mi;
        if (m < ntok) {
            int t = toks[m];
            float4 v;
            v.x = hsum2(oacc[mi][0]);
            v.y = hsum2(oacc[mi][1]);
            v.z = hsum2(oacc[mi][2]);
            v.w = hsum2(oacc[mi][3]);
            reinterpret_cast<float4*>(out)[(t * D_DIM + dd0) >> 2] = v;
        }
    }
}

// ---------------- launcher ----------------
extern "C" void kernel_launch(void* const* d_in, const int* in_sizes, int n_in,
                              void* d_out, int out_size) {
    const float* x  = (const float*)d_in[0];
    const float* w1 = (const float*)d_in[1];
    const float* w2 = (const float*)d_in[2];
    const float* wg = (const float*)d_in[3];
    const float* bg = (const float*)d_in[4];
    float* out = (float*)d_out;

    cudaFuncSetAttribute(moe_kernel, cudaFuncAttributeMaxDynamicSharedMemorySize,
                         SMEM_BYTES);

    zero_cnt_kernel<<<1, E_EXP>>>();
    router_kernel<<<B_TOK / THREADS, THREADS>>>(x, wg, bg);
    dim3 grid(E_EXP, B_TOK / TM);  // capacity grid: no token dropped under any imbalance
    moe_kernel<<<grid, THREADS, SMEM_BYTES>>>(x, w1, w2, out);
}

// round 3
// speedup vs baseline: 1.2433x; 1.2433x over previous
#include <cuda_runtime.h>
#include <math.h>

#define B_TOK 32768
#define D_DIM 128
#define H_DIM 512
#define E_EXP 16
#define TM 64
#define KH 64
#define NCHUNK (H_DIM / KH)
#define THREADS 256

// ---------------- device scratch (no allocation allowed) ----------------
__device__ int g_cnt[E_EXP];
__device__ int g_tok[E_EXP * B_TOK];

// ---------------- f32x2 helpers (sm_103a packed fp32 pipe) ----------------
__device__ __forceinline__ unsigned long long ffma2(unsigned long long a,
                                                    unsigned long long b,
                                                    unsigned long long c) {
    unsigned long long d;
    asm("fma.rn.f32x2 %0, %1, %2, %3;" : "=l"(d) : "l"(a), "l"(b), "l"(c));
    return d;
}
__device__ __forceinline__ float hsum2(unsigned long long v) {
    unsigned int lo, hi;
    asm("mov.b64 {%0, %1}, %2;" : "=r"(lo), "=r"(hi) : "l"(v));
    return __uint_as_float(lo) + __uint_as_float(hi);
}

// ---------------- kernel 0: reset counters (graph replay safe) ----------------
__global__ void zero_cnt_kernel() {
    if (threadIdx.x < E_EXP) g_cnt[threadIdx.x] = 0;
}

// ---------------- kernel 1: router (argmax of x@wg+bg), warp-aggregated buckets ----
__global__ __launch_bounds__(THREADS) void router_kernel(
    const float* __restrict__ x, const float* __restrict__ wg,
    const float* __restrict__ bg) {
    __shared__ float wgs[D_DIM * E_EXP];
    __shared__ float bgs[E_EXP];
    int tid = threadIdx.x;
    for (int i = tid; i < D_DIM * E_EXP; i += THREADS) wgs[i] = wg[i];
    if (tid < E_EXP) bgs[tid] = bg[tid];
    __syncthreads();

    int b = blockIdx.x * THREADS + tid;
    float acc[E_EXP];
#pragma unroll
    for (int e = 0; e < E_EXP; e++) acc[e] = bgs[e];

    const float4* xr = reinterpret_cast<const float4*>(x) + (size_t)b * (D_DIM / 4);
#pragma unroll 4
    for (int dq = 0; dq < D_DIM / 4; dq++) {
        float4 xv = xr[dq];
#pragma unroll
        for (int e = 0; e < E_EXP; e++) {
            acc[e] += xv.x * wgs[(dq * 4 + 0) * E_EXP + e];
            acc[e] += xv.y * wgs[(dq * 4 + 1) * E_EXP + e];
            acc[e] += xv.z * wgs[(dq * 4 + 2) * E_EXP + e];
            acc[e] += xv.w * wgs[(dq * 4 + 3) * E_EXP + e];
        }
    }
    int best = 0; float bv = acc[0];
#pragma unroll
    for (int e = 1; e < E_EXP; e++)
        if (acc[e] > bv) { bv = acc[e]; best = e; }  // strict > keeps first max (top_k tie rule)

    // warp-aggregated atomic append into per-expert bucket
    unsigned lane = tid & 31;
    unsigned mask = __match_any_sync(0xffffffffu, best);
    int leader = __ffs(mask) - 1;
    int rank = __popc(mask & ((1u << lane) - 1u));
    int base = 0;
    if ((int)lane == leader) base = atomicAdd(&g_cnt[best], __popc(mask));
    base = __shfl_sync(0xffffffffu, base, leader);
    g_tok[best * B_TOK + base + rank] = b;
}

// ---------------- kernel 2: grouped fused MLP ----------------
// CTA = one 64-token tile of one expert. SMEM: Xs[64][128] | Ws (pair-interleaved
// weight chunk, 8192 f) | Hs[64][64] | toks[64]. Both GEMMs run on fma.rn.f32x2.
// Thread->column maps are LANE-STRIDED so B-operand LDS.64 is conflict-free.
#define SMEM_FLOATS (TM * D_DIM + 8192 + TM * KH)
#define SMEM_BYTES (SMEM_FLOATS * 4 + TM * 4)

extern __shared__ float smem[];

__global__ __launch_bounds__(THREADS) void moe_kernel(
    const float* __restrict__ x, const float* __restrict__ w1,
    const float* __restrict__ w2, float* __restrict__ out) {
    int e = blockIdx.x;
    int cnt = g_cnt[e];
    int start = blockIdx.y * TM;
    if (start >= cnt) return;
    int ntok = min(TM, cnt - start);
    int tid = threadIdx.x;

    float* Xs = smem;                 // [m][d] row-major, 64*128
    float* Ws = smem + TM * D_DIM;    // pair-interleaved weight chunk, 8192 floats
    float* Hs = Ws + 8192;            // [m][j] row-major, 64*64
    int* toks = (int*)(Hs + TM * KH); // 64 ints

    if (tid < TM) toks[tid] = (tid < ntok) ? g_tok[e * B_TOK + start + tid] : -1;
    __syncthreads();

    // gather X rows (zeros for padded slots)
#pragma unroll
    for (int it = 0; it < 8; it++) {
        int idx = tid + it * THREADS;   // 0..2047
        int m = idx >> 5;               // token in tile
        int q = idx & 31;               // float4 within row
        int t = toks[m];
        float4 v = (t >= 0) ? reinterpret_cast<const float4*>(x)[t * 32 + q]
                            : make_float4(0.f, 0.f, 0.f, 0.f);
        reinterpret_cast<float4*>(Xs)[m * 32 + q] = v;
    }

    const float* w1e = w1 + (size_t)e * D_DIM * H_DIM;
    const float* w2e = w2 + (size_t)e * H_DIM * D_DIM;

    // phase-1 thread map: 16x16 grid; j-set = {tx, tx+16, tx+32, tx+48} (lane-strided)
    int tx = tid & 15, ty = tid >> 4;
    int m0 = ty * 4;
    // phase-2 thread map: 32x8 grid; d-set = {lane, lane+32, lane+64, lane+96}
    int lane = tid & 31;
    int m0b = (tid >> 5) * 8;

    unsigned long long oacc[8][4];
#pragma unroll
    for (int i = 0; i < 8; i++)
#pragma unroll
        for (int j = 0; j < 4; j++) oacc[i][j] = 0ull;

    for (int c = 0; c < NCHUNK; c++) {
        int h0 = c * KH;
        __syncthreads();  // Ws/Hs free of previous-phase readers; Xs stores visible (c==0)

        // ---- load W1 chunk, pair-interleave along d: Ws[(dp*KH + j)*2 + (d&1)]
#pragma unroll
        for (int it = 0; it < 8; it++) {
            int idx = tid + it * THREADS;  // 0..2047
            int d = idx >> 4;              // 0..127
            int q = idx & 15;              // j-quad
            float4 v = reinterpret_cast<const float4*>(w1e + d * H_DIM + h0)[q];
            int dp = d >> 1, ln = d & 1;
            Ws[(dp * KH + q * 4 + 0) * 2 + ln] = v.x;
            Ws[(dp * KH + q * 4 + 1) * 2 + ln] = v.y;
            Ws[(dp * KH + q * 4 + 2) * 2 + ln] = v.z;
            Ws[(dp * KH + q * 4 + 3) * 2 + ln] = v.w;
        }
        __syncthreads();

        // ---- phase 1: Hs = gelu(X @ W1chunk), f32x2 over d-pairs
        unsigned long long acc[4][4];
#pragma unroll
        for (int i = 0; i < 4; i++)
#pragma unroll
            for (int j = 0; j < 4; j++) acc[i][j] = 0ull;

#pragma unroll 8
        for (int dp = 0; dp < D_DIM / 2; dp++) {
            unsigned long long a2[4], b2[4];
#pragma unroll
            for (int mi = 0; mi < 4; mi++)
                a2[mi] = *reinterpret_cast<const unsigned long long*>(
                    &Xs[(m0 + mi) * D_DIM + 2 * dp]);
#pragma unroll
            for (int ji = 0; ji < 4; ji++)
                b2[ji] = *reinterpret_cast<const unsigned long long*>(
                    &Ws[(dp * KH + tx + 16 * ji) * 2]);   // lane stride 8B: conflict-free
#pragma unroll
            for (int mi = 0; mi < 4; mi++)
#pragma unroll
                for (int ji = 0; ji < 4; ji++)
                    acc[mi][ji] = ffma2(a2[mi], b2[ji], acc[mi][ji]);
        }
#pragma unroll
        for (int mi = 0; mi < 4; mi++)
#pragma unroll
            for (int ji = 0; ji < 4; ji++) {
                float h = hsum2(acc[mi][ji]);
                float g = 0.5f * h * (1.0f + erff(h * 0.70710678118654752440f));
                Hs[(m0 + mi) * KH + tx + 16 * ji] = g;
            }
        __syncthreads();

        // ---- load W2 chunk, pair-interleave along j: Ws[(jp*D + dd)*2 + (j&1)]
#pragma unroll
        for (int it = 0; it < 8; it++) {
            int idx = tid + it * THREADS;  // 0..2047
            int j = idx >> 5;              // 0..63
            int q = idx & 31;              // dd-quad
            float4 v = reinterpret_cast<const float4*>(w2e + (size_t)(h0 + j) * D_DIM)[q];
            int jp = j >> 1, ln = j & 1;
            Ws[(jp * D_DIM + q * 4 + 0) * 2 + ln] = v.x;
            Ws[(jp * D_DIM + q * 4 + 1) * 2 + ln] = v.y;
            Ws[(jp * D_DIM + q * 4 + 2) * 2 + ln] = v.z;
            Ws[(jp * D_DIM + q * 4 + 3) * 2 + ln] = v.w;
        }
        __syncthreads();

        // ---- phase 2: out += Hs @ W2chunk, f32x2 over j-pairs (persistent packed acc)
#pragma unroll 8
        for (int jp = 0; jp < KH / 2; jp++) {
            unsigned long long a2[8], b2[4];
#pragma unroll
            for (int mi = 0; mi < 8; mi++)
                a2[mi] = *reinterpret_cast<const unsigned long long*>(
                    &Hs[(m0b + mi) * KH + 2 * jp]);
#pragma unroll
            for (int di = 0; di < 4; di++)
                b2[di] = *reinterpret_cast<const unsigned long long*>(
                    &Ws[(jp * D_DIM + lane + 32 * di) * 2]);  // lane stride 8B: conflict-free
#pragma unroll
            for (int mi = 0; mi < 8; mi++)
#pragma unroll
                for (int di = 0; di < 4; di++)
                    oacc[mi][di] = ffma2(a2[mi], b2[di], oacc[mi][di]);
        }
    }

    // epilogue: horizontal add of even/odd-j partials, scatter to output rows
    // columns lane+32*di -> consecutive lanes write consecutive floats (coalesced)
#pragma unroll
    for (int mi = 0; mi < 8; mi++) {
        int m = m0b + mi;
        if (m < ntok) {
            int t = toks[m];
#pragma unroll
            for (int di = 0; di < 4; di++)
                out[(size_t)t * D_DIM + lane + 32 * di] = hsum2(oacc[mi][di]);
        }
    }
}

// ---------------- launcher ----------------
extern "C" void kernel_launch(void* const* d_in, const int* in_sizes, int n_in,
                              void* d_out, int out_size) {
    const float* x  = (const float*)d_in[0];
    const float* w1 = (const float*)d_in[1];
    const float* w2 = (const float*)d_in[2];
    const float* wg = (const float*)d_in[3];
    const float* bg = (const float*)d_in[4];
    float* out = (float*)d_out;

    cudaFuncSetAttribute(moe_kernel, cudaFuncAttributeMaxDynamicSharedMemorySize,
                         SMEM_BYTES);

    zero_cnt_kernel<<<1, E_EXP>>>();
    router_kernel<<<B_TOK / THREADS, THREADS>>>(x, wg, bg);
    dim3 grid(E_EXP, B_TOK / TM);  // capacity grid: no token dropped under any imbalance
    moe_kernel<<<grid, THREADS, SMEM_BYTES>>>(x, w1, w2, out);
}